// round 13
// baseline (speedup 1.0000x reference)
#include <cuda_runtime.h>

// ConvCapsMatrix: EM-routing matrix capsules, fully fused.
// B=4, 14x14 -> 12x12, KH=KW=3, IC=OC=32, M=4 (P=16), ITERS=3.
//
// R12 -> R13: R12 showed the expanded-quadratic logp (not the CTA split)
// caused the alu-pipe inflation -> full revert to R10's proven config
// (nmu/hisg logp, redux-max, 256 thr x 2 CTA/SM). New single change:
// x patch stored PRE-DUPLICATED as f32x2 pairs (xdup[n][x*4+y]=(v,v)),
// killing 16 mov.b64 broadcasts per chunk (ALU) and shortening the
// V-compute block from ~52 to ~40 issue slots.
// History: R6 W transpose 229.6->162.3; R9 reg-hoist ->139.3; R10 (256,2)
// + redux-max ->121.3; R11/R12 expanded-quadratic experiments regressed.
//
// Roles in a 256-thread CTA (one CTA per output position):
//  streaming: (nn = warp 0..7, o = lane 0..31); 36 chunks per warp
//  stats:     (o = tid>>4 and (tid>>4)+16, p = tid&15)

#define NPOS  576           // 4 * 12 * 12
#define EPSF  1e-8f

// dynamic smem layout (float offsets)
#define SM_XD    0          // [9216]  x patch duplicated: u64[n*16 + x*4+y] = (v,v)
#define SM_A     9216       // [288]   a patch
#define SM_NMU   9504       // [576]   -mu, [o*18+p] (u64-pair readable)
#define SM_HSG   10080      // [576]   0.5/sig2, same layout
#define SM_SLOG  10656      // [32]
#define SM_LOGA  10688      // [32]
#define SM_RED1  10720      // [8*544] per-warp S1 partials [w*544+o*17+p], p=16 -> Rs
#define SM_RED2  15072      // [8*544] per-warp S2 partials
#define SM_TOT   19424      // floats -> 77696 bytes (x2 CTAs = 155KB/SM)

typedef unsigned long long u64;

// transposed W: ulonglong2[(n*4+y)*32 + o] = W[n][o][y][0..3]  (576 KB scratch)
__device__ ulonglong2 g_Wt[288 * 4 * 32];

__device__ __forceinline__ u64 pk2(float lo, float hi) {
    u64 r; asm("mov.b64 %0, {%1, %2};" : "=l"(r) : "f"(lo), "f"(hi)); return r;
}
__device__ __forceinline__ void upk2(u64 v, float& lo, float& hi) {
    asm("mov.b64 {%0, %1}, %2;" : "=f"(lo), "=f"(hi) : "l"(v));
}
__device__ __forceinline__ u64 fma2(u64 a, u64 b, u64 c) {
    u64 d; asm("fma.rn.f32x2 %0, %1, %2, %3;" : "=l"(d) : "l"(a), "l"(b), "l"(c)); return d;
}
__device__ __forceinline__ u64 mul2(u64 a, u64 b) {
    u64 d; asm("mul.rn.f32x2 %0, %1, %2;" : "=l"(d) : "l"(a), "l"(b)); return d;
}
__device__ __forceinline__ u64 add2(u64 a, u64 b) {
    u64 d; asm("add.rn.f32x2 %0, %1, %2;" : "=l"(d) : "l"(a), "l"(b)); return d;
}
// warp-max of a float via integer redux (monotone order-preserving key)
__device__ __forceinline__ float warp_max_f32(float s) {
    unsigned sb = __float_as_uint(s);
    unsigned key = sb ^ ((unsigned)(((int)sb) >> 31) | 0x80000000u);
    unsigned mk;
    asm("redux.sync.max.u32 %0, %1, 0xffffffff;" : "=r"(mk) : "r"(key));
    unsigned mb = mk ^ ((unsigned)(((int)(~mk)) >> 31) | 0x80000000u);
    return __uint_as_float(mb);
}

__global__ void __launch_bounds__(256)
transpose_W_kernel(const float4* __restrict__ W4)
{
    int idx = blockIdx.x * 256 + threadIdx.x;   // (n*4+y)*32 + o
    if (idx >= 288 * 4 * 32) return;
    int o  = idx & 31;
    int ny = idx >> 5;
    int y  = ny & 3;
    int n  = ny >> 2;
    float4 r = W4[(n * 32 + o) * 4 + y];
    ulonglong2 v;
    v.x = pk2(r.x, r.y);
    v.y = pk2(r.z, r.w);
    g_Wt[idx] = v;                               // coalesced 16B store
}

extern __shared__ float smem[];

__global__ void __launch_bounds__(256, 2)
caps_kernel(const float* __restrict__ x, const float* __restrict__ a,
            const float* __restrict__ bu_g, const float* __restrict__ ba_g,
            float* __restrict__ out)
{
    const int tid = threadIdx.x;
    const int pos = blockIdx.x;
    const int b  = pos / 144;
    const int hw = pos - b * 144;
    const int h  = hw / 12;
    const int w  = hw - h * 12;

    // ---- load x / a patches into smem; x stored as duplicated f32x2 ----
    {
        u64* xd = reinterpret_cast<u64*>(smem + SM_XD);
        for (int idx = tid; idx < 4608; idx += 256) {
            int n = idx >> 4, q = idx & 15;
            int k = n / 96;
            int r = n - k * 96;
            int l = r >> 5;
            int c = r & 31;
            float v = x[(((b * 14 + h + k) * 14 + (w + l)) * 32 + c) * 16 + q];
            xd[idx] = pk2(v, v);
        }
    }
    for (int n = tid; n < 288; n += 256) {
        int k = n / 96;
        int r = n - k * 96;
        int l = r >> 5;
        int c = r & 31;
        smem[SM_A + n] = a[((b * 14 + h + k) * 14 + (w + l)) * 32 + c];
    }
    __syncthreads();

    const int lane_o  = tid & 31;   // streaming: output capsule
    const int warp_nn = tid >> 5;   // streaming: n within chunk (0..7)
    const int oa = tid >> 4;        // stats role: first o (0..15)
    const int ob = oa + 16;         // stats role: second o
    const int p3 = tid & 15;

    const u64* nmu_p = reinterpret_cast<const u64*>(smem + SM_NMU) + lane_o * 9;
    const u64* hsg_p = reinterpret_cast<const u64*>(smem + SM_HSG) + lane_o * 9;
    float* row1 = smem + SM_RED1 + warp_nn * 544 + lane_o * 17;  // bank-bijective over o
    float* row2 = smem + SM_RED2 + warp_nn * 544 + lane_o * 17;
    // coalesced W: lane o reads g_Wt[(n*4+y)*32 + o]; chunk advance = 8*128 ull2
    const ulonglong2* Wbase = g_Wt + (warp_nn << 7) + lane_o;

    for (int pass = 0; pass < 3; ++pass) {
        u64 s1p[8], s2p[8];
        #pragma unroll
        for (int j = 0; j < 8; ++j) { s1p[j] = 0ull; s2p[j] = 0ull; }
        float rs_reg = 0.f;

        // pass-invariant per-o constants, hoisted to registers
        float pre = 0.f;
        u64 nmu_r[8], hsg_r[8];
        if (pass > 0) {
            pre = smem[SM_LOGA + lane_o] - 0.5f * smem[SM_SLOG + lane_o];
            #pragma unroll
            for (int j = 0; j < 8; ++j) { nmu_r[j] = nmu_p[j]; hsg_r[j] = hsg_p[j]; }
        }

        // prefetch chunk 0's W rows (4 coalesced LDG.128)
        const ulonglong2* wp = Wbase;
        ulonglong2 wy0 = wp[0], wy1 = wp[32], wy2 = wp[64], wy3 = wp[96];

        #pragma unroll 1
        for (int ch = 0; ch < 36; ++ch) {
            const int n = ch * 8 + warp_nn;
            // duplicated x pairs: broadcast LDS.128, two (v,v) u64 per load
            const ulonglong2* xd =
                reinterpret_cast<const ulonglong2*>(smem + SM_XD) + (n << 3);

            // V[n, lane_o, :] packed: vp[2x+hh] = (v[4x+2hh], v[4x+2hh+1])
            u64 vp[8];
            #pragma unroll
            for (int xx = 0; xx < 4; ++xx) {
                ulonglong2 p01 = xd[xx * 2];
                ulonglong2 p23 = xd[xx * 2 + 1];
                u64 lo = mul2(p01.x, wy0.x);
                lo = fma2(p01.y, wy1.x, lo);
                lo = fma2(p23.x, wy2.x, lo);
                lo = fma2(p23.y, wy3.x, lo);
                u64 hi = mul2(p01.x, wy0.y);
                hi = fma2(p01.y, wy1.y, hi);
                hi = fma2(p23.x, wy2.y, hi);
                hi = fma2(p23.y, wy3.y, hi);
                vp[xx * 2]     = lo;
                vp[xx * 2 + 1] = hi;
            }

            // wy dead: issue next chunk's W loads now (covered by logp/accum)
            if (ch < 35) {
                wp += 1024;
                wy0 = wp[0]; wy1 = wp[32]; wy2 = wp[64]; wy3 = wp[96];
            }

            float Ra;
            if (pass == 0) {
                Ra = smem[SM_A + n] * 0.03125f;   // R uniform = 1/OC
            } else {
                // t = sum_p 0.5 * d^2 / sig2  (0.5 folded into hsg_r)
                u64 t2 = 0ull;
                #pragma unroll
                for (int j = 0; j < 8; ++j) {
                    u64 d = add2(vp[j], nmu_r[j]);   // mu stored negated
                    t2 = fma2(mul2(d, d), hsg_r[j], t2);
                }
                float tl, th; upk2(t2, tl, th);
                float s = pre - (tl + th);
                // softmax over o == softmax over warp lanes
                float m = warp_max_f32(s);           // single-op integer redux
                float e = __expf(s - m);
                float sum = e;
                #pragma unroll
                for (int off = 16; off; off >>= 1)
                    sum += __shfl_xor_sync(0xffffffffu, sum, off);
                Ra = __fdividef(e, sum) * smem[SM_A + n];
            }

            rs_reg += Ra;
            u64 Ra2 = pk2(Ra, Ra);
            #pragma unroll
            for (int j = 0; j < 8; ++j) {
                u64 rv = mul2(Ra2, vp[j]);
                s1p[j] = add2(s1p[j], rv);
                s2p[j] = fma2(rv, vp[j], s2p[j]);
            }
        }

        // ---- cross-warp reduction: STS partials to this warp's private row ----
        row1[16] = rs_reg;                   // Rs in the p=16 pad slot
        #pragma unroll
        for (int j = 0; j < 8; ++j) {
            float lo, hi;
            upk2(s1p[j], lo, hi);
            row1[2 * j] = lo; row1[2 * j + 1] = hi;
            upk2(s2p[j], lo, hi);
            row2[2 * j] = lo; row2[2 * j + 1] = hi;
        }
        __syncthreads();

        // ---- gather + stats: thread handles (oa, p3) and (ob, p3) ----
        #pragma unroll
        for (int half = 0; half < 2; ++half) {
            const int o3 = half ? ob : oa;
            float sS1 = 0.f, sS2 = 0.f, sRs = 0.f;
            {
                const float* g1 = smem + SM_RED1 + o3 * 17 + p3;
                const float* g2 = smem + SM_RED2 + o3 * 17 + p3;
                const float* gr = smem + SM_RED1 + o3 * 17 + 16;
                #pragma unroll
                for (int ww = 0; ww < 8; ++ww) {
                    sS1 += g1[ww * 544];
                    sS2 += g2[ww * 544];
                    sRs += gr[ww * 544];
                }
            }
            float Rsv   = sRs + EPSF;
            float invRs = 1.0f / Rsv;
            float mu    = sS1 * invRs;
            float sig2  = fmaxf(sS2 * invRs - mu * mu, 0.0f) + EPSF;
            float sl    = __logf(sig2);
            #pragma unroll
            for (int off = 8; off; off >>= 1)   // reduce log sig2 over 16 p-lanes
                sl += __shfl_xor_sync(0xffffffffu, sl, off);

            if (pass < 2) {
                smem[SM_NMU + o3 * 18 + p3] = -mu;
                smem[SM_HSG + o3 * 18 + p3] = __fdividef(0.5f, sig2);
                if (p3 == 0) {
                    smem[SM_SLOG + o3] = sl;
                    float cost = Rsv * fmaf(0.5f, sl, 16.0f * bu_g[o3]);
                    float aout = 1.0f / (1.0f + __expf(cost - ba_g[o3]));
                    smem[SM_LOGA + o3] = __logf(aout + EPSF);
                }
            } else {
                out[pos * 512 + o3 * 16 + p3] = mu;
                if (p3 == 0) {
                    float cost = Rsv * fmaf(0.5f, sl, 16.0f * bu_g[o3]);
                    out[NPOS * 512 + pos * 32 + o3] =
                        1.0f / (1.0f + __expf(cost - ba_g[o3]));
                }
            }
        }
        if (pass < 2) __syncthreads();   // stats visible before next pass streams
    }
}

extern "C" void kernel_launch(void* const* d_in, const int* in_sizes, int n_in,
                              void* d_out, int out_size)
{
    (void)in_sizes; (void)n_in; (void)out_size;
    const float* x  = (const float*)d_in[0];
    const float* a  = (const float*)d_in[1];
    const float* W  = (const float*)d_in[2];
    const float* bu = (const float*)d_in[3];
    const float* ba = (const float*)d_in[4];
    transpose_W_kernel<<<144, 256>>>((const float4*)W);
    cudaFuncSetAttribute(caps_kernel,
                         cudaFuncAttributeMaxDynamicSharedMemorySize,
                         SM_TOT * (int)sizeof(float));
    caps_kernel<<<NPOS, 256, SM_TOT * sizeof(float)>>>(x, a, bu, ba, (float*)d_out);
}

// round 15
// speedup vs baseline: 1.0240x; 1.0240x over previous
#include <cuda_runtime.h>

// ConvCapsMatrix: EM-routing matrix capsules, fully fused.
// B=4, 14x14 -> 12x12, KH=KW=3, IC=OC=32, M=4 (P=16), ITERS=3.
//
// R13 -> R14: R13's x-pre-duplication broke FFMA2 pairing (fma-time +60%)
// -> full revert to R10's exact form (best measured: 121.3us). One change:
// softmax denominator via fixed-point redux.sync.add.u32 — after max-sub,
// e in (0,1], sum <= 32 -> 2^24 scaling is exact to ~2e-6 rel; replaces the
// 5-deep shfl+add chain (10 ops, ~130cyc) with cvt+redux+cvt (~4 ops).
// History: R6 W transpose 229.6->162.3; R9 reg-hoist ->139.3; R10 (256,2)
// + redux-max ->121.3; R11-R13 experiments regressed (reverted).
//
// Roles in a 256-thread CTA (one CTA per output position):
//  streaming: (nn = warp 0..7, o = lane 0..31); 36 chunks per warp
//  stats:     (o = tid>>4 and (tid>>4)+16, p = tid&15)

#define NPOS  576           // 4 * 12 * 12
#define EPSF  1e-8f

// dynamic smem layout (float offsets)
#define SM_XP    0          // [4608]  x patch [n][p]
#define SM_A     4608       // [288]   a patch
#define SM_NMU   4896       // [576]   -mu, [o*18+p] (u64-pair readable)
#define SM_HSG   5472       // [576]   0.5/sig2, same layout
#define SM_SLOG  6048       // [32]
#define SM_LOGA  6080       // [32]
#define SM_RED1  6112       // [8*544] per-warp S1 partials [w*544+o*17+p], p=16 -> Rs
#define SM_RED2  10464      // [8*544] per-warp S2 partials
#define SM_TOT   14816      // floats -> 59264 bytes (x2 CTAs = 118KB/SM)

typedef unsigned long long u64;

// transposed W: ulonglong2[(n*4+y)*32 + o] = W[n][o][y][0..3]  (576 KB scratch)
__device__ ulonglong2 g_Wt[288 * 4 * 32];

__device__ __forceinline__ u64 pk2(float lo, float hi) {
    u64 r; asm("mov.b64 %0, {%1, %2};" : "=l"(r) : "f"(lo), "f"(hi)); return r;
}
__device__ __forceinline__ void upk2(u64 v, float& lo, float& hi) {
    asm("mov.b64 {%0, %1}, %2;" : "=f"(lo), "=f"(hi) : "l"(v));
}
__device__ __forceinline__ u64 fma2(u64 a, u64 b, u64 c) {
    u64 d; asm("fma.rn.f32x2 %0, %1, %2, %3;" : "=l"(d) : "l"(a), "l"(b), "l"(c)); return d;
}
__device__ __forceinline__ u64 mul2(u64 a, u64 b) {
    u64 d; asm("mul.rn.f32x2 %0, %1, %2;" : "=l"(d) : "l"(a), "l"(b)); return d;
}
__device__ __forceinline__ u64 add2(u64 a, u64 b) {
    u64 d; asm("add.rn.f32x2 %0, %1, %2;" : "=l"(d) : "l"(a), "l"(b)); return d;
}
// warp-max of a float via integer redux (monotone order-preserving key)
__device__ __forceinline__ float warp_max_f32(float s) {
    unsigned sb = __float_as_uint(s);
    unsigned key = sb ^ ((unsigned)(((int)sb) >> 31) | 0x80000000u);
    unsigned mk;
    asm("redux.sync.max.u32 %0, %1, 0xffffffff;" : "=r"(mk) : "r"(key));
    unsigned mb = mk ^ ((unsigned)(((int)(~mk)) >> 31) | 0x80000000u);
    return __uint_as_float(mb);
}
// warp-sum of e in (0,1] via 2^24 fixed point (exact to ~2e-6 rel; sum<=32)
__device__ __forceinline__ float warp_sum_unit(float e) {
    unsigned ei = __float2uint_rn(e * 16777216.0f);
    unsigned isum;
    asm("redux.sync.add.u32 %0, %1, 0xffffffff;" : "=r"(isum) : "r"(ei));
    return __uint2float_rn(isum);   // caller folds the 2^24 scale
}

__global__ void __launch_bounds__(256)
transpose_W_kernel(const float4* __restrict__ W4)
{
    int idx = blockIdx.x * 256 + threadIdx.x;   // (n*4+y)*32 + o
    if (idx >= 288 * 4 * 32) return;
    int o  = idx & 31;
    int ny = idx >> 5;
    int y  = ny & 3;
    int n  = ny >> 2;
    float4 r = W4[(n * 32 + o) * 4 + y];
    ulonglong2 v;
    v.x = pk2(r.x, r.y);
    v.y = pk2(r.z, r.w);
    g_Wt[idx] = v;                               // coalesced 16B store
}

extern __shared__ float smem[];

__global__ void __launch_bounds__(256, 2)
caps_kernel(const float* __restrict__ x, const float* __restrict__ a,
            const float* __restrict__ bu_g, const float* __restrict__ ba_g,
            float* __restrict__ out)
{
    const int tid = threadIdx.x;
    const int pos = blockIdx.x;
    const int b  = pos / 144;
    const int hw = pos - b * 144;
    const int h  = hw / 12;
    const int w  = hw - h * 12;

    // ---- load x / a patches into smem (coalesced) ----
    for (int idx = tid; idx < 4608; idx += 256) {
        int n = idx >> 4, q = idx & 15;
        int k = n / 96;
        int r = n - k * 96;
        int l = r >> 5;
        int c = r & 31;
        smem[SM_XP + idx] = x[(((b * 14 + h + k) * 14 + (w + l)) * 32 + c) * 16 + q];
    }
    for (int n = tid; n < 288; n += 256) {
        int k = n / 96;
        int r = n - k * 96;
        int l = r >> 5;
        int c = r & 31;
        smem[SM_A + n] = a[((b * 14 + h + k) * 14 + (w + l)) * 32 + c];
    }
    __syncthreads();

    const int lane_o  = tid & 31;   // streaming: output capsule
    const int warp_nn = tid >> 5;   // streaming: n within chunk (0..7)
    const int oa = tid >> 4;        // stats role: first o (0..15)
    const int ob = oa + 16;         // stats role: second o
    const int p3 = tid & 15;

    const u64* nmu_p = reinterpret_cast<const u64*>(smem + SM_NMU) + lane_o * 9;
    const u64* hsg_p = reinterpret_cast<const u64*>(smem + SM_HSG) + lane_o * 9;
    float* row1 = smem + SM_RED1 + warp_nn * 544 + lane_o * 17;  // bank-bijective over o
    float* row2 = smem + SM_RED2 + warp_nn * 544 + lane_o * 17;
    // coalesced W: lane o reads g_Wt[(n*4+y)*32 + o]; chunk advance = 8*128 ull2
    const ulonglong2* Wbase = g_Wt + (warp_nn << 7) + lane_o;

    for (int pass = 0; pass < 3; ++pass) {
        u64 s1p[8], s2p[8];
        #pragma unroll
        for (int j = 0; j < 8; ++j) { s1p[j] = 0ull; s2p[j] = 0ull; }
        float rs_reg = 0.f;

        // pass-invariant per-o constants, hoisted to registers
        float pre = 0.f;
        u64 nmu_r[8], hsg_r[8];
        if (pass > 0) {
            pre = smem[SM_LOGA + lane_o] - 0.5f * smem[SM_SLOG + lane_o];
            #pragma unroll
            for (int j = 0; j < 8; ++j) { nmu_r[j] = nmu_p[j]; hsg_r[j] = hsg_p[j]; }
        }

        // prefetch chunk 0's W rows (4 coalesced LDG.128)
        const ulonglong2* wp = Wbase;
        ulonglong2 wy0 = wp[0], wy1 = wp[32], wy2 = wp[64], wy3 = wp[96];

        #pragma unroll 1
        for (int ch = 0; ch < 36; ++ch) {
            const int n = ch * 8 + warp_nn;
            const float4* xv = reinterpret_cast<const float4*>(smem + SM_XP) + (n << 2);

            // V[n, lane_o, :] packed: vp[2x+hh] = (v[4x+2hh], v[4x+2hh+1])
            u64 vp[8];
            #pragma unroll
            for (int xx = 0; xx < 4; ++xx) {
                float4 xr = xv[xx];
                u64 b0 = pk2(xr.x, xr.x);
                u64 b1 = pk2(xr.y, xr.y);
                u64 b2 = pk2(xr.z, xr.z);
                u64 b3 = pk2(xr.w, xr.w);
                u64 lo = mul2(b0, wy0.x);
                lo = fma2(b1, wy1.x, lo);
                lo = fma2(b2, wy2.x, lo);
                lo = fma2(b3, wy3.x, lo);
                u64 hi = mul2(b0, wy0.y);
                hi = fma2(b1, wy1.y, hi);
                hi = fma2(b2, wy2.y, hi);
                hi = fma2(b3, wy3.y, hi);
                vp[xx * 2]     = lo;
                vp[xx * 2 + 1] = hi;
            }

            // wy dead: issue next chunk's W loads now (covered by logp/accum)
            if (ch < 35) {
                wp += 1024;
                wy0 = wp[0]; wy1 = wp[32]; wy2 = wp[64]; wy3 = wp[96];
            }

            float Ra;
            if (pass == 0) {
                Ra = smem[SM_A + n] * 0.03125f;   // R uniform = 1/OC
            } else {
                // t = sum_p 0.5 * d^2 / sig2  (0.5 folded into hsg_r)
                u64 t2 = 0ull;
                #pragma unroll
                for (int j = 0; j < 8; ++j) {
                    u64 d = add2(vp[j], nmu_r[j]);   // mu stored negated
                    t2 = fma2(mul2(d, d), hsg_r[j], t2);
                }
                float tl, th; upk2(t2, tl, th);
                float s = pre - (tl + th);
                // softmax over o == softmax over warp lanes (both via redux)
                float m = warp_max_f32(s);
                float e = __expf(s - m);                   // max lane -> e = 1
                float isum = warp_sum_unit(e);             // sum(e) * 2^24
                Ra = __fdividef(e * 16777216.0f * smem[SM_A + n], isum);
            }

            rs_reg += Ra;
            u64 Ra2 = pk2(Ra, Ra);
            #pragma unroll
            for (int j = 0; j < 8; ++j) {
                u64 rv = mul2(Ra2, vp[j]);
                s1p[j] = add2(s1p[j], rv);
                s2p[j] = fma2(rv, vp[j], s2p[j]);
            }
        }

        // ---- cross-warp reduction: STS partials to this warp's private row ----
        row1[16] = rs_reg;                   // Rs in the p=16 pad slot
        #pragma unroll
        for (int j = 0; j < 8; ++j) {
            float lo, hi;
            upk2(s1p[j], lo, hi);
            row1[2 * j] = lo; row1[2 * j + 1] = hi;
            upk2(s2p[j], lo, hi);
            row2[2 * j] = lo; row2[2 * j + 1] = hi;
        }
        __syncthreads();

        // ---- gather + stats: thread handles (oa, p3) and (ob, p3) ----
        #pragma unroll
        for (int half = 0; half < 2; ++half) {
            const int o3 = half ? ob : oa;
            float sS1 = 0.f, sS2 = 0.f, sRs = 0.f;
            {
                const float* g1 = smem + SM_RED1 + o3 * 17 + p3;
                const float* g2 = smem + SM_RED2 + o3 * 17 + p3;
                const float* gr = smem + SM_RED1 + o3 * 17 + 16;
                #pragma unroll
                for (int ww = 0; ww < 8; ++ww) {
                    sS1 += g1[ww * 544];
                    sS2 += g2[ww * 544];
                    sRs += gr[ww * 544];
                }
            }
            float Rsv   = sRs + EPSF;
            float invRs = 1.0f / Rsv;
            float mu    = sS1 * invRs;
            float sig2  = fmaxf(sS2 * invRs - mu * mu, 0.0f) + EPSF;
            float sl    = __logf(sig2);
            #pragma unroll
            for (int off = 8; off; off >>= 1)   // reduce log sig2 over 16 p-lanes
                sl += __shfl_xor_sync(0xffffffffu, sl, off);

            if (pass < 2) {
                smem[SM_NMU + o3 * 18 + p3] = -mu;
                smem[SM_HSG + o3 * 18 + p3] = __fdividef(0.5f, sig2);
                if (p3 == 0) {
                    smem[SM_SLOG + o3] = sl;
                    float cost = Rsv * fmaf(0.5f, sl, 16.0f * bu_g[o3]);
                    float aout = 1.0f / (1.0f + __expf(cost - ba_g[o3]));
                    smem[SM_LOGA + o3] = __logf(aout + EPSF);
                }
            } else {
                out[pos * 512 + o3 * 16 + p3] = mu;
                if (p3 == 0) {
                    float cost = Rsv * fmaf(0.5f, sl, 16.0f * bu_g[o3]);
                    out[NPOS * 512 + pos * 32 + o3] =
                        1.0f / (1.0f + __expf(cost - ba_g[o3]));
                }
            }
        }
        if (pass < 2) __syncthreads();   // stats visible before next pass streams
    }
}

extern "C" void kernel_launch(void* const* d_in, const int* in_sizes, int n_in,
                              void* d_out, int out_size)
{
    (void)in_sizes; (void)n_in; (void)out_size;
    const float* x  = (const float*)d_in[0];
    const float* a  = (const float*)d_in[1];
    const float* W  = (const float*)d_in[2];
    const float* bu = (const float*)d_in[3];
    const float* ba = (const float*)d_in[4];
    transpose_W_kernel<<<144, 256>>>((const float4*)W);
    cudaFuncSetAttribute(caps_kernel,
                         cudaFuncAttributeMaxDynamicSharedMemorySize,
                         SM_TOT * (int)sizeof(float));
    caps_kernel<<<NPOS, 256, SM_TOT * sizeof(float)>>>(x, a, bu, ba, (float*)d_out);
}

// round 16
// speedup vs baseline: 1.7561x; 1.7149x over previous
#include <cuda_runtime.h>

// ConvCapsMatrix: EM-routing matrix capsules, fully fused.
// B=4, 14x14 -> 12x12, KH=KW=3, IC=OC=32, M=4 (P=16), ITERS=3.
//
// R15 -> R16: exact revert to the R10 champion (121.3us). R15's profile had
// near-identical pipe shares to R10 but 1.63x wall time — uniform scaling
// consistent with SM clock droop on the brokered GPU, not with worse code;
// still, the fixed-point-sum change was at best neutral, so it is dropped.
// This bench re-validates the baseline and discriminates machine noise.
// History: R6 W transpose 229.6->162.3; R9 reg-hoist ->139.3; R10 (256,2)
// + redux-max ->121.3; R11-R15 experiments all regressed (reverted).
//
// Roles in a 256-thread CTA (one CTA per output position):
//  streaming: (nn = warp 0..7, o = lane 0..31); 36 chunks per warp
//  stats:     (o = tid>>4 and (tid>>4)+16, p = tid&15)

#define NPOS  576           // 4 * 12 * 12
#define EPSF  1e-8f

// dynamic smem layout (float offsets)
#define SM_XP    0          // [4608]  x patch [n][p]
#define SM_A     4608       // [288]   a patch
#define SM_NMU   4896       // [576]   -mu, [o*18+p] (u64-pair readable)
#define SM_HSG   5472       // [576]   0.5/sig2, same layout
#define SM_SLOG  6048       // [32]
#define SM_LOGA  6080       // [32]
#define SM_RED1  6112       // [8*544] per-warp S1 partials [w*544+o*17+p], p=16 -> Rs
#define SM_RED2  10464      // [8*544] per-warp S2 partials
#define SM_TOT   14816      // floats -> 59264 bytes (x2 CTAs = 118KB/SM)

typedef unsigned long long u64;

// transposed W: ulonglong2[(n*4+y)*32 + o] = W[n][o][y][0..3]  (576 KB scratch)
__device__ ulonglong2 g_Wt[288 * 4 * 32];

__device__ __forceinline__ u64 pk2(float lo, float hi) {
    u64 r; asm("mov.b64 %0, {%1, %2};" : "=l"(r) : "f"(lo), "f"(hi)); return r;
}
__device__ __forceinline__ void upk2(u64 v, float& lo, float& hi) {
    asm("mov.b64 {%0, %1}, %2;" : "=f"(lo), "=f"(hi) : "l"(v));
}
__device__ __forceinline__ u64 fma2(u64 a, u64 b, u64 c) {
    u64 d; asm("fma.rn.f32x2 %0, %1, %2, %3;" : "=l"(d) : "l"(a), "l"(b), "l"(c)); return d;
}
__device__ __forceinline__ u64 mul2(u64 a, u64 b) {
    u64 d; asm("mul.rn.f32x2 %0, %1, %2;" : "=l"(d) : "l"(a), "l"(b)); return d;
}
__device__ __forceinline__ u64 add2(u64 a, u64 b) {
    u64 d; asm("add.rn.f32x2 %0, %1, %2;" : "=l"(d) : "l"(a), "l"(b)); return d;
}
// warp-max of a float via integer redux (monotone order-preserving key)
__device__ __forceinline__ float warp_max_f32(float s) {
    unsigned sb = __float_as_uint(s);
    unsigned key = sb ^ ((unsigned)(((int)sb) >> 31) | 0x80000000u);
    unsigned mk;
    asm("redux.sync.max.u32 %0, %1, 0xffffffff;" : "=r"(mk) : "r"(key));
    unsigned mb = mk ^ ((unsigned)(((int)(~mk)) >> 31) | 0x80000000u);
    return __uint_as_float(mb);
}

__global__ void __launch_bounds__(256)
transpose_W_kernel(const float4* __restrict__ W4)
{
    int idx = blockIdx.x * 256 + threadIdx.x;   // (n*4+y)*32 + o
    if (idx >= 288 * 4 * 32) return;
    int o  = idx & 31;
    int ny = idx >> 5;
    int y  = ny & 3;
    int n  = ny >> 2;
    float4 r = W4[(n * 32 + o) * 4 + y];
    ulonglong2 v;
    v.x = pk2(r.x, r.y);
    v.y = pk2(r.z, r.w);
    g_Wt[idx] = v;                               // coalesced 16B store
}

extern __shared__ float smem[];

__global__ void __launch_bounds__(256, 2)
caps_kernel(const float* __restrict__ x, const float* __restrict__ a,
            const float* __restrict__ bu_g, const float* __restrict__ ba_g,
            float* __restrict__ out)
{
    const int tid = threadIdx.x;
    const int pos = blockIdx.x;
    const int b  = pos / 144;
    const int hw = pos - b * 144;
    const int h  = hw / 12;
    const int w  = hw - h * 12;

    // ---- load x / a patches into smem (coalesced) ----
    for (int idx = tid; idx < 4608; idx += 256) {
        int n = idx >> 4, q = idx & 15;
        int k = n / 96;
        int r = n - k * 96;
        int l = r >> 5;
        int c = r & 31;
        smem[SM_XP + idx] = x[(((b * 14 + h + k) * 14 + (w + l)) * 32 + c) * 16 + q];
    }
    for (int n = tid; n < 288; n += 256) {
        int k = n / 96;
        int r = n - k * 96;
        int l = r >> 5;
        int c = r & 31;
        smem[SM_A + n] = a[((b * 14 + h + k) * 14 + (w + l)) * 32 + c];
    }
    __syncthreads();

    const int lane_o  = tid & 31;   // streaming: output capsule
    const int warp_nn = tid >> 5;   // streaming: n within chunk (0..7)
    const int oa = tid >> 4;        // stats role: first o (0..15)
    const int ob = oa + 16;         // stats role: second o
    const int p3 = tid & 15;

    const u64* nmu_p = reinterpret_cast<const u64*>(smem + SM_NMU) + lane_o * 9;
    const u64* hsg_p = reinterpret_cast<const u64*>(smem + SM_HSG) + lane_o * 9;
    float* row1 = smem + SM_RED1 + warp_nn * 544 + lane_o * 17;  // bank-bijective over o
    float* row2 = smem + SM_RED2 + warp_nn * 544 + lane_o * 17;
    // coalesced W: lane o reads g_Wt[(n*4+y)*32 + o]; chunk advance = 8*128 ull2
    const ulonglong2* Wbase = g_Wt + (warp_nn << 7) + lane_o;

    for (int pass = 0; pass < 3; ++pass) {
        u64 s1p[8], s2p[8];
        #pragma unroll
        for (int j = 0; j < 8; ++j) { s1p[j] = 0ull; s2p[j] = 0ull; }
        float rs_reg = 0.f;

        // pass-invariant per-o constants, hoisted to registers
        float pre = 0.f;
        u64 nmu_r[8], hsg_r[8];
        if (pass > 0) {
            pre = smem[SM_LOGA + lane_o] - 0.5f * smem[SM_SLOG + lane_o];
            #pragma unroll
            for (int j = 0; j < 8; ++j) { nmu_r[j] = nmu_p[j]; hsg_r[j] = hsg_p[j]; }
        }

        // prefetch chunk 0's W rows (4 coalesced LDG.128)
        const ulonglong2* wp = Wbase;
        ulonglong2 wy0 = wp[0], wy1 = wp[32], wy2 = wp[64], wy3 = wp[96];

        #pragma unroll 1
        for (int ch = 0; ch < 36; ++ch) {
            const int n = ch * 8 + warp_nn;
            const float4* xv = reinterpret_cast<const float4*>(smem + SM_XP) + (n << 2);

            // V[n, lane_o, :] packed: vp[2x+hh] = (v[4x+2hh], v[4x+2hh+1])
            u64 vp[8];
            #pragma unroll
            for (int xx = 0; xx < 4; ++xx) {
                float4 xr = xv[xx];
                u64 b0 = pk2(xr.x, xr.x);
                u64 b1 = pk2(xr.y, xr.y);
                u64 b2 = pk2(xr.z, xr.z);
                u64 b3 = pk2(xr.w, xr.w);
                u64 lo = mul2(b0, wy0.x);
                lo = fma2(b1, wy1.x, lo);
                lo = fma2(b2, wy2.x, lo);
                lo = fma2(b3, wy3.x, lo);
                u64 hi = mul2(b0, wy0.y);
                hi = fma2(b1, wy1.y, hi);
                hi = fma2(b2, wy2.y, hi);
                hi = fma2(b3, wy3.y, hi);
                vp[xx * 2]     = lo;
                vp[xx * 2 + 1] = hi;
            }

            // wy dead: issue next chunk's W loads now (covered by logp/accum)
            if (ch < 35) {
                wp += 1024;
                wy0 = wp[0]; wy1 = wp[32]; wy2 = wp[64]; wy3 = wp[96];
            }

            float Ra;
            if (pass == 0) {
                Ra = smem[SM_A + n] * 0.03125f;   // R uniform = 1/OC
            } else {
                // t = sum_p 0.5 * d^2 / sig2  (0.5 folded into hsg_r)
                u64 t2 = 0ull;
                #pragma unroll
                for (int j = 0; j < 8; ++j) {
                    u64 d = add2(vp[j], nmu_r[j]);   // mu stored negated
                    t2 = fma2(mul2(d, d), hsg_r[j], t2);
                }
                float tl, th; upk2(t2, tl, th);
                float s = pre - (tl + th);
                // softmax over o == softmax over warp lanes
                float m = warp_max_f32(s);           // single-op integer redux
                float e = __expf(s - m);
                float sum = e;
                #pragma unroll
                for (int off = 16; off; off >>= 1)
                    sum += __shfl_xor_sync(0xffffffffu, sum, off);
                Ra = __fdividef(e, sum) * smem[SM_A + n];
            }

            rs_reg += Ra;
            u64 Ra2 = pk2(Ra, Ra);
            #pragma unroll
            for (int j = 0; j < 8; ++j) {
                u64 rv = mul2(Ra2, vp[j]);
                s1p[j] = add2(s1p[j], rv);
                s2p[j] = fma2(rv, vp[j], s2p[j]);
            }
        }

        // ---- cross-warp reduction: STS partials to this warp's private row ----
        row1[16] = rs_reg;                   // Rs in the p=16 pad slot
        #pragma unroll
        for (int j = 0; j < 8; ++j) {
            float lo, hi;
            upk2(s1p[j], lo, hi);
            row1[2 * j] = lo; row1[2 * j + 1] = hi;
            upk2(s2p[j], lo, hi);
            row2[2 * j] = lo; row2[2 * j + 1] = hi;
        }
        __syncthreads();

        // ---- gather + stats: thread handles (oa, p3) and (ob, p3) ----
        #pragma unroll
        for (int half = 0; half < 2; ++half) {
            const int o3 = half ? ob : oa;
            float sS1 = 0.f, sS2 = 0.f, sRs = 0.f;
            {
                const float* g1 = smem + SM_RED1 + o3 * 17 + p3;
                const float* g2 = smem + SM_RED2 + o3 * 17 + p3;
                const float* gr = smem + SM_RED1 + o3 * 17 + 16;
                #pragma unroll
                for (int ww = 0; ww < 8; ++ww) {
                    sS1 += g1[ww * 544];
                    sS2 += g2[ww * 544];
                    sRs += gr[ww * 544];
                }
            }
            float Rsv   = sRs + EPSF;
            float invRs = 1.0f / Rsv;
            float mu    = sS1 * invRs;
            float sig2  = fmaxf(sS2 * invRs - mu * mu, 0.0f) + EPSF;
            float sl    = __logf(sig2);
            #pragma unroll
            for (int off = 8; off; off >>= 1)   // reduce log sig2 over 16 p-lanes
                sl += __shfl_xor_sync(0xffffffffu, sl, off);

            if (pass < 2) {
                smem[SM_NMU + o3 * 18 + p3] = -mu;
                smem[SM_HSG + o3 * 18 + p3] = __fdividef(0.5f, sig2);
                if (p3 == 0) {
                    smem[SM_SLOG + o3] = sl;
                    float cost = Rsv * fmaf(0.5f, sl, 16.0f * bu_g[o3]);
                    float aout = 1.0f / (1.0f + __expf(cost - ba_g[o3]));
                    smem[SM_LOGA + o3] = __logf(aout + EPSF);
                }
            } else {
                out[pos * 512 + o3 * 16 + p3] = mu;
                if (p3 == 0) {
                    float cost = Rsv * fmaf(0.5f, sl, 16.0f * bu_g[o3]);
                    out[NPOS * 512 + pos * 32 + o3] =
                        1.0f / (1.0f + __expf(cost - ba_g[o3]));
                }
            }
        }
        if (pass < 2) __syncthreads();   // stats visible before next pass streams
    }
}

extern "C" void kernel_launch(void* const* d_in, const int* in_sizes, int n_in,
                              void* d_out, int out_size)
{
    (void)in_sizes; (void)n_in; (void)out_size;
    const float* x  = (const float*)d_in[0];
    const float* a  = (const float*)d_in[1];
    const float* W  = (const float*)d_in[2];
    const float* bu = (const float*)d_in[3];
    const float* ba = (const float*)d_in[4];
    transpose_W_kernel<<<144, 256>>>((const float4*)W);
    cudaFuncSetAttribute(caps_kernel,
                         cudaFuncAttributeMaxDynamicSharedMemorySize,
                         SM_TOT * (int)sizeof(float));
    caps_kernel<<<NPOS, 256, SM_TOT * sizeof(float)>>>(x, a, bu, ba, (float*)d_out);
}